// round 13
// baseline (speedup 1.0000x reference)
#include <cuda_runtime.h>
#include <math_constants.h>

#define TT 4096
#define NB 8
#define NEGF (-CUDART_INF_F)

// fused accumulator: bits[56:63] = arrival count, bits[0:55] = biased fixed-point sum
__device__ unsigned long long g_sum = 0ULL;

#define FP_SCALE 16777216.0f          /* 2^24 */
#define FP_BIAS  (1LL << 45)
#define CNT_ONE  (1ULL << 56)
#define SUM_MASK ((1ULL << 56) - 1ULL)

__device__ __forceinline__ float pen(float yv, float idx, float eps) {
    return fmaxf(0.0f, fabsf(yv - idx) - eps);
}

__global__ void __launch_bounds__(512, 1)
custom_loss_kernel(const float* __restrict__ X,   // (8, 1, 4096)
                   const float* __restrict__ Y,   // (8, 2)
                   const unsigned* __restrict__ epsb,
                   float* __restrict__ out)       // scalar
{
    const int b    = blockIdx.x;
    const int tid  = threadIdx.x;
    const int w    = tid >> 5;        // 16 warps
    const int lane = tid & 31;

    const float* xb = X + b * TT;
    const float y0 = Y[2 * b + 0];
    const float y1 = Y[2 * b + 1];

    // eps arrives as int32 or float32 bits; int 5 as float bits is a denormal.
    const unsigned eb = *epsb;
    const float    ef = __uint_as_float(eb);
    const float eps = (ef >= 1e-6f && ef <= 1e9f) ? ef : (float)(int)eb;

    const int sl = (w << 8) + (lane << 3);       // 8 contiguous elems per lane

    // main segment: 2x float4 (aligned, in-bounds), front-batched
    float xa[8];
#pragma unroll
    for (int q = 0; q < 2; q++) {
        float4 v = reinterpret_cast<const float4*>(xb + sl)[q];
        xa[4*q+0] = v.x; xa[4*q+1] = v.y; xa[4*q+2] = v.z; xa[4*q+3] = v.w;
    }
    // tail x[sl+8 .. sl+12] for the +5 shift; only sl = TT-8 would be OOB and
    // its tail values are provably unused there (j >= TT). Clamp the address.
    const int ts = (sl <= TT - 13) ? sl + 8 : TT - 8;
    float xt[5];
    {
        float4 v = *reinterpret_cast<const float4*>(xb + ts);
        xt[0] = v.x; xt[1] = v.y; xt[2] = v.z; xt[3] = v.w;
        xt[4] = xb[ts + 4];
    }

    // descending scan over 8 elems:
    //   a'[k] = x[k] + .5*pen(y0,k)      masked to k >= 5
    //   b'[k] = x[k+5] + .5*pen(y1,k+5)  valid while k+5 < TT
    //   P = max_{i<=k in seg} a'[i]+b'[k];  A = max a';  Bm = max b'
    float P = NEGF, A = NEGF, suffB = NEGF;
    const float slf = (float)sl;
#pragma unroll
    for (int t = 7; t >= 0; t--) {
        const int   k  = sl + t;
        const float kf = slf + (float)t;
        const float xj = (t <= 2) ? xa[t + 5] : xt[t - 3];
        const float bv = (k + 5 < TT) ? (xj + 0.5f * pen(y1, kf + 5.0f, eps)) : NEGF;
        suffB = fmaxf(suffB, bv);
        const float av = (k >= 5) ? (xa[t] + 0.5f * pen(y0, kf, eps)) : NEGF;
        A = fmaxf(A, av);
        P = fmaxf(P, av + suffB);
    }
    float Bm = suffB;

    // fold the UNMASKED init term a[1] + b[6] into the sl==0 lane's P
    if (sl == 0) {
        const float init = (xa[1] + 0.5f * pen(y0, 1.0f, eps))
                         + (xa[6] + 0.5f * pen(y1, 6.0f, eps));
        P = fmaxf(P, init);
    }

    // ordered warp combine, UNPREDICATED: out-of-range shfl_down returns own
    // value; those lanes' triples never feed lane 0's tree, so exactness holds.
#pragma unroll
    for (int off = 1; off < 32; off <<= 1) {
        const float Pr = __shfl_down_sync(0xffffffffu, P,  off);
        const float Ar = __shfl_down_sync(0xffffffffu, A,  off);
        const float Br = __shfl_down_sync(0xffffffffu, Bm, off);
        P  = fmaxf(fmaxf(P, Pr), A + Br);
        A  = fmaxf(A, Ar);
        Bm = fmaxf(Bm, Br);
    }

    __shared__ float sP[16], sA[16], sB[16];
    if (lane == 0) { sP[w] = P; sA[w] = A; sB[w] = Bm; }
    __syncthreads();                               // plain BAR.SYNC: measured fastest

    // warp 0: lanes 0..15 pick up one triple each; 4-level ordered tree combine
    if (w == 0) {
        const int q = lane & 15;
        float p  = sP[q];
        float a  = sA[q];
        float bm = sB[q];
#pragma unroll
        for (int off = 1; off < 16; off <<= 1) {
            const float Pr = __shfl_down_sync(0xffffffffu, p,  off);
            const float Ar = __shfl_down_sync(0xffffffffu, a,  off);
            const float Br = __shfl_down_sync(0xffffffffu, bm, off);
            p  = fmaxf(fmaxf(p, Pr), a + Br);
            a  = fmaxf(a, Ar);
            bm = fmaxf(bm, Br);
        }
        if (lane == 0) {
            // fixed-point encode; one fused atomic carries count + sum.
            const long long ll = llrintf(p * FP_SCALE) + FP_BIAS;
            const unsigned long long v   = CNT_ONE + (unsigned long long)ll;
            const unsigned long long old = atomicAdd(&g_sum, v);
            if ((old >> 56) == NB - 1) {             // this CTA completed the sum
                const long long tot =
                    (long long)((old + v) & SUM_MASK) - (long long)NB * FP_BIAS;
                out[0] = (float)((double)tot * (1.0 / (FP_SCALE * (double)NB)));
                g_sum = 0ULL;                        // re-arm for next replay
            }
        }
    }
}

extern "C" void kernel_launch(void* const* d_in, const int* in_sizes, int n_in,
                              void* d_out, int out_size) {
    const float*    w_phi = (const float*)d_in[0];
    const float*    y     = (const float*)d_in[1];
    const unsigned* epsb  = (const unsigned*)d_in[2];
    float*          out   = (float*)d_out;
    custom_loss_kernel<<<NB, 512>>>(w_phi, y, epsb, out);
}

// round 14
// speedup vs baseline: 1.0337x; 1.0337x over previous
#include <cuda_runtime.h>
#include <math_constants.h>

#define TT 4096
#define NB 8
#define NEGF (-CUDART_INF_F)

// fused accumulator: bits[56:63] = arrival count, bits[0:55] = biased fixed-point sum
__device__ unsigned long long g_sum = 0ULL;

#define FP_SCALE 16777216.0f          /* 2^24 */
#define FP_BIAS  (1LL << 45)
#define CNT_ONE  (1ULL << 56)
#define SUM_MASK ((1ULL << 56) - 1ULL)

__device__ __forceinline__ float pen(float yv, float idx, float eps) {
    return fmaxf(0.0f, fabsf(yv - idx) - eps);
}

__global__ void __launch_bounds__(512, 1)
custom_loss_kernel(const float* __restrict__ X,   // (8, 1, 4096)
                   const float* __restrict__ Y,   // (8, 2)
                   const unsigned* __restrict__ epsb,
                   float* __restrict__ out)       // scalar
{
    const int b    = blockIdx.x;
    const int tid  = threadIdx.x;
    const int w    = tid >> 5;        // 16 warps
    const int lane = tid & 31;

    const float* xb = X + b * TT;
    const float y0 = Y[2 * b + 0];
    const float y1 = Y[2 * b + 1];

    // eps arrives as int32 or float32 bits; int 5 as float bits is a denormal.
    const unsigned eb = *epsb;
    const float    ef = __uint_as_float(eb);
    const float eps = (ef >= 1e-6f && ef <= 1e9f) ? ef : (float)(int)eb;

    const int sl = (w << 8) + (lane << 3);       // 8 contiguous elems per lane

    // main segment: 2x float4 (aligned, in-bounds), front-batched
    float xa[8];
#pragma unroll
    for (int q = 0; q < 2; q++) {
        float4 v = reinterpret_cast<const float4*>(xb + sl)[q];
        xa[4*q+0] = v.x; xa[4*q+1] = v.y; xa[4*q+2] = v.z; xa[4*q+3] = v.w;
    }
    // tail x[sl+8 .. sl+12] for the +5 shift; only sl = TT-8 would be OOB and
    // its tail values are provably unused there (j >= TT). Clamp the address.
    const int ts = (sl <= TT - 13) ? sl + 8 : TT - 8;
    float xt[5];
    {
        float4 v = *reinterpret_cast<const float4*>(xb + ts);
        xt[0] = v.x; xt[1] = v.y; xt[2] = v.z; xt[3] = v.w;
        xt[4] = xb[ts + 4];
    }

    // descending scan over 8 elems:
    //   a'[k] = x[k] + .5*pen(y0,k)      masked to k >= 5
    //   b'[k] = x[k+5] + .5*pen(y1,k+5)  valid while k+5 < TT
    //   P = max_{i<=k in seg} a'[i]+b'[k];  A = max a';  Bm = max b'
    float P = NEGF, A = NEGF, suffB = NEGF;
    const float slf = (float)sl;
#pragma unroll
    for (int t = 7; t >= 0; t--) {
        const int   k  = sl + t;
        const float kf = slf + (float)t;
        const float xj = (t <= 2) ? xa[t + 5] : xt[t - 3];
        const float bv = (k + 5 < TT) ? (xj + 0.5f * pen(y1, kf + 5.0f, eps)) : NEGF;
        suffB = fmaxf(suffB, bv);
        const float av = (k >= 5) ? (xa[t] + 0.5f * pen(y0, kf, eps)) : NEGF;
        A = fmaxf(A, av);
        P = fmaxf(P, av + suffB);
    }
    float Bm = suffB;

    // fold the UNMASKED init term a[1] + b[6] into the sl==0 lane's P
    if (sl == 0) {
        const float init = (xa[1] + 0.5f * pen(y0, 1.0f, eps))
                         + (xa[6] + 0.5f * pen(y1, 6.0f, eps));
        P = fmaxf(P, init);
    }

    // ordered warp combine, UNPREDICATED: out-of-range shfl_down returns own
    // value; those lanes' triples never feed lane 0's tree, so exactness holds.
#pragma unroll
    for (int off = 1; off < 32; off <<= 1) {
        const float Pr = __shfl_down_sync(0xffffffffu, P,  off);
        const float Ar = __shfl_down_sync(0xffffffffu, A,  off);
        const float Br = __shfl_down_sync(0xffffffffu, Bm, off);
        P  = fmaxf(fmaxf(P, Pr), A + Br);
        A  = fmaxf(A, Ar);
        Bm = fmaxf(Bm, Br);
    }

    __shared__ float sP[16], sA[16], sB[16];
    if (lane == 0) { sP[w] = P; sA[w] = A; sB[w] = Bm; }
    __syncthreads();                               // plain BAR.SYNC: measured fastest

    // warp 0: lanes 0..15 pick up one triple each; 4-level ordered tree combine
    if (w == 0) {
        const int q = lane & 15;
        float p  = sP[q];
        float a  = sA[q];
        float bm = sB[q];
#pragma unroll
        for (int off = 1; off < 16; off <<= 1) {
            const float Pr = __shfl_down_sync(0xffffffffu, p,  off);
            const float Ar = __shfl_down_sync(0xffffffffu, a,  off);
            const float Br = __shfl_down_sync(0xffffffffu, bm, off);
            p  = fmaxf(fmaxf(p, Pr), a + Br);
            a  = fmaxf(a, Ar);
            bm = fmaxf(bm, Br);
        }
        if (lane == 0) {
            // fixed-point encode; one fused atomic carries count + sum.
            const long long ll = llrintf(p * FP_SCALE) + FP_BIAS;
            const unsigned long long v   = CNT_ONE + (unsigned long long)ll;
            const unsigned long long old = atomicAdd(&g_sum, v);
            if ((old >> 56) == NB - 1) {             // this CTA completed the sum
                const long long tot =
                    (long long)((old + v) & SUM_MASK) - (long long)NB * FP_BIAS;
                out[0] = (float)((double)tot * (1.0 / (FP_SCALE * (double)NB)));
                g_sum = 0ULL;                        // re-arm for next replay
            }
        }
    }
}

extern "C" void kernel_launch(void* const* d_in, const int* in_sizes, int n_in,
                              void* d_out, int out_size) {
    const float*    w_phi = (const float*)d_in[0];
    const float*    y     = (const float*)d_in[1];
    const unsigned* epsb  = (const unsigned*)d_in[2];
    float*          out   = (float*)d_out;
    custom_loss_kernel<<<NB, 512>>>(w_phi, y, epsb, out);
}

// round 15
// speedup vs baseline: 1.0539x; 1.0196x over previous
#include <cuda_runtime.h>
#include <math_constants.h>

#define TT 4096
#define NB 8
#define NEGF (-CUDART_INF_F)

// fused accumulator: bits[56:63] = arrival count, bits[0:55] = biased fixed-point sum
__device__ unsigned long long g_sum = 0ULL;

#define FP_SCALE 16777216.0f          /* 2^24 */
#define FP_BIAS  (1LL << 45)
#define CNT_ONE  (1ULL << 56)
#define SUM_MASK ((1ULL << 56) - 1ULL)

__device__ __forceinline__ float pen(float yv, float idx, float eps) {
    return fmaxf(0.0f, fabsf(yv - idx) - eps);
}

__global__ void __launch_bounds__(512, 1)
custom_loss_kernel(const float* __restrict__ X,   // (8, 1, 4096)
                   const float* __restrict__ Y,   // (8, 2)
                   const unsigned* __restrict__ epsb,
                   float* __restrict__ out)       // scalar
{
    const int b    = blockIdx.x;
    const int tid  = threadIdx.x;
    const int w    = tid >> 5;        // 16 warps
    const int lane = tid & 31;

    const float* xb = X + b * TT;
    const float y0 = Y[2 * b + 0];
    const float y1 = Y[2 * b + 1];

    // eps arrives as int32 or float32 bits; int 5 as float bits is a denormal.
    const unsigned eb = *epsb;
    const float    ef = __uint_as_float(eb);
    const float eps = (ef >= 1e-6f && ef <= 1e9f) ? ef : (float)(int)eb;

    const int sl = (w << 8) + (lane << 3);       // 8 contiguous elems per lane

    // main segment: 2x float4 (aligned, in-bounds), front-batched
    float xa[8];
#pragma unroll
    for (int q = 0; q < 2; q++) {
        float4 v = reinterpret_cast<const float4*>(xb + sl)[q];
        xa[4*q+0] = v.x; xa[4*q+1] = v.y; xa[4*q+2] = v.z; xa[4*q+3] = v.w;
    }
    // tail x[sl+8 .. sl+12] for the +5 shift; only sl = TT-8 would be OOB and
    // its tail values are provably unused there (j >= TT). Clamp the address.
    const int ts = (sl <= TT - 13) ? sl + 8 : TT - 8;
    float xt[5];
    {
        float4 v = *reinterpret_cast<const float4*>(xb + ts);
        xt[0] = v.x; xt[1] = v.y; xt[2] = v.z; xt[3] = v.w;
        xt[4] = xb[ts + 4];
    }

    // descending scan over 8 elems:
    //   a'[k] = x[k] + .5*pen(y0,k)      masked to k >= 5
    //   b'[k] = x[k+5] + .5*pen(y1,k+5)  valid while k+5 < TT
    //   P = max_{i<=k in seg} a'[i]+b'[k];  A = max a';  Bm = max b'
    float P = NEGF, A = NEGF, suffB = NEGF;
    const float slf = (float)sl;
#pragma unroll
    for (int t = 7; t >= 0; t--) {
        const int   k  = sl + t;
        const float kf = slf + (float)t;
        const float xj = (t <= 2) ? xa[t + 5] : xt[t - 3];
        const float bv = (k + 5 < TT) ? (xj + 0.5f * pen(y1, kf + 5.0f, eps)) : NEGF;
        suffB = fmaxf(suffB, bv);
        const float av = (k >= 5) ? (xa[t] + 0.5f * pen(y0, kf, eps)) : NEGF;
        A = fmaxf(A, av);
        P = fmaxf(P, av + suffB);
    }
    float Bm = suffB;

    // fold the UNMASKED init term a[1] + b[6] into the sl==0 lane's P
    if (sl == 0) {
        const float init = (xa[1] + 0.5f * pen(y0, 1.0f, eps))
                         + (xa[6] + 0.5f * pen(y1, 6.0f, eps));
        P = fmaxf(P, init);
    }

    // ordered warp combine, UNPREDICATED: out-of-range shfl_down returns own
    // value; those lanes' triples never feed lane 0's tree, so exactness holds.
#pragma unroll
    for (int off = 1; off < 32; off <<= 1) {
        const float Pr = __shfl_down_sync(0xffffffffu, P,  off);
        const float Ar = __shfl_down_sync(0xffffffffu, A,  off);
        const float Br = __shfl_down_sync(0xffffffffu, Bm, off);
        P  = fmaxf(fmaxf(P, Pr), A + Br);
        A  = fmaxf(A, Ar);
        Bm = fmaxf(Bm, Br);
    }

    __shared__ float sP[16], sA[16], sB[16];
    if (lane == 0) { sP[w] = P; sA[w] = A; sB[w] = Bm; }
    __syncthreads();                               // plain BAR.SYNC: measured fastest

    // warp 0: lanes 0..15 pick up one triple each; 4-level ordered tree combine
    if (w == 0) {
        const int q = lane & 15;
        float p  = sP[q];
        float a  = sA[q];
        float bm = sB[q];
#pragma unroll
        for (int off = 1; off < 16; off <<= 1) {
            const float Pr = __shfl_down_sync(0xffffffffu, p,  off);
            const float Ar = __shfl_down_sync(0xffffffffu, a,  off);
            const float Br = __shfl_down_sync(0xffffffffu, bm, off);
            p  = fmaxf(fmaxf(p, Pr), a + Br);
            a  = fmaxf(a, Ar);
            bm = fmaxf(bm, Br);
        }
        if (lane == 0) {
            // fixed-point encode; one fused atomic carries count + sum.
            const long long ll = llrintf(p * FP_SCALE) + FP_BIAS;
            const unsigned long long v   = CNT_ONE + (unsigned long long)ll;
            const unsigned long long old = atomicAdd(&g_sum, v);
            if ((old >> 56) == NB - 1) {             // this CTA completed the sum
                const long long tot =
                    (long long)((old + v) & SUM_MASK) - (long long)NB * FP_BIAS;
                out[0] = (float)((double)tot * (1.0 / (FP_SCALE * (double)NB)));
                g_sum = 0ULL;                        // re-arm for next replay
            }
        }
    }
}

extern "C" void kernel_launch(void* const* d_in, const int* in_sizes, int n_in,
                              void* d_out, int out_size) {
    const float*    w_phi = (const float*)d_in[0];
    const float*    y     = (const float*)d_in[1];
    const unsigned* epsb  = (const unsigned*)d_in[2];
    float*          out   = (float*)d_out;
    custom_loss_kernel<<<NB, 512>>>(w_phi, y, epsb, out);
}